// round 2
// baseline (speedup 1.0000x reference)
#include <cuda_runtime.h>
#include <cstdint>

#define N0      4096
#define NUM     8192
#define DD      512
#define CLASSES 100

// ---- device scratch (allowed: __device__ globals, no runtime alloc) ----
__device__ float g_x2[(size_t)NUM * DD];       // concat(x, x_ul)   16 MB
__device__ float g_bb[NUM];                    // squared norms
__device__ float g_y2[NUM];                    // concat(y, y_ul)
__device__ float g_S[(size_t)NUM * NUM];       // score matrix     256 MB
__device__ float g_musum[CLASSES * DD];
__device__ float g_cnt[CLASSES];
__device__ float g_mu[CLASSES * DD];
__device__ float g_mumu[CLASSES];
__device__ float g_ptgm[NUM];
__device__ float g_ptknn[NUM];

// packed f32x2 fma: d.lo = fma(a.lo,b.lo,c.lo); d.hi likewise
__device__ __forceinline__ void ffma2(unsigned long long& d,
                                      unsigned long long a,
                                      unsigned long long b,
                                      unsigned long long c) {
    asm("fma.rn.f32x2 %0, %1, %2, %3;" : "=l"(d) : "l"(a), "l"(b), "l"(c));
}
__device__ __forceinline__ unsigned long long splat2(float x) {
    unsigned long long r;
    unsigned int xb = __float_as_uint(x);
    asm("mov.b64 %0, {%1, %1};" : "=l"(r) : "r"(xb));
    return r;
}

// ---------------------------------------------------------------
// build x2 = [x ; lam*x + (1-lam)*x[perm]], norms, y2 lower half
// ---------------------------------------------------------------
__global__ void build_kernel(const float* __restrict__ x, const float* __restrict__ y,
                             const float* __restrict__ lamp, const int* __restrict__ perm) {
    int row = blockIdx.x;
    int tid = threadIdx.x;
    float ss = 0.f;
    float4* dst = (float4*)(g_x2 + (size_t)row * DD);
    if (row < N0) {
        const float4* src = (const float4*)(x + (size_t)row * DD);
        float4 v = src[tid];
        dst[tid] = v;
        ss = v.x * v.x + v.y * v.y + v.z * v.z + v.w * v.w;
        if (tid == 0) g_y2[row] = y[row];
    } else {
        int j = row - N0;
        float lam = *lamp;
        float oml = 1.f - lam;
        int p = perm[j];
        const float4* a = (const float4*)(x + (size_t)j * DD);
        const float4* b = (const float4*)(x + (size_t)p * DD);
        float4 va = a[tid], vb = b[tid], v;
        v.x = va.x * lam + vb.x * oml;
        v.y = va.y * lam + vb.y * oml;
        v.z = va.z * lam + vb.z * oml;
        v.w = va.w * lam + vb.w * oml;
        dst[tid] = v;
        ss = v.x * v.x + v.y * v.y + v.z * v.z + v.w * v.w;
    }
    __shared__ float red[128];
    red[tid] = ss;
    __syncthreads();
    #pragma unroll
    for (int s = 64; s > 0; s >>= 1) {
        if (tid < s) red[tid] += red[tid + s];
        __syncthreads();
    }
    if (tid == 0) g_bb[row] = red[0];
}

// ---------------------------------------------------------------
// score GEMM:  S[i][j] = bb[j] - 2 * dot(Q[i], B[j])
// 128x128 tile, 256 threads, 8x8 micro-tile via packed f32x2 FMA
// ---------------------------------------------------------------
__global__ __launch_bounds__(256, 2) void gemm_dist(int qoff, int M, int N) {
    __shared__ float As[2][16][128];
    __shared__ float Bs[2][16][128];
    int tid = threadIdx.x;
    int tx = tid & 15, ty = tid >> 4;
    const float* Qb = g_x2 + (size_t)(qoff + blockIdx.y * 128) * DD;
    const float* Bb = g_x2 + (size_t)(blockIdx.x * 128) * DD;

    unsigned long long acc[8][4];   // each holds 2 adjacent N columns
    #pragma unroll
    for (int u = 0; u < 8; u++)
        #pragma unroll
        for (int v = 0; v < 4; v++) acc[u][v] = 0ull;

    int lrow = tid >> 2;          // 0..63
    int lk   = (tid & 3) * 4;     // 0,4,8,12

    // preload chunk 0
    #pragma unroll
    for (int l = 0; l < 2; l++) {
        int row = lrow + l * 64;
        float4 va = *(const float4*)(Qb + (size_t)row * DD + lk);
        As[0][lk + 0][row] = va.x; As[0][lk + 1][row] = va.y;
        As[0][lk + 2][row] = va.z; As[0][lk + 3][row] = va.w;
        float4 vb = *(const float4*)(Bb + (size_t)row * DD + lk);
        Bs[0][lk + 0][row] = vb.x; Bs[0][lk + 1][row] = vb.y;
        Bs[0][lk + 2][row] = vb.z; Bs[0][lk + 3][row] = vb.w;
    }
    __syncthreads();

    int buf = 0;
    for (int k0 = 16; k0 <= DD; k0 += 16) {
        if (k0 < DD) {
            int nb = buf ^ 1;
            #pragma unroll
            for (int l = 0; l < 2; l++) {
                int row = lrow + l * 64;
                float4 va = *(const float4*)(Qb + (size_t)row * DD + k0 + lk);
                As[nb][lk + 0][row] = va.x; As[nb][lk + 1][row] = va.y;
                As[nb][lk + 2][row] = va.z; As[nb][lk + 3][row] = va.w;
                float4 vb = *(const float4*)(Bb + (size_t)row * DD + k0 + lk);
                Bs[nb][lk + 0][row] = vb.x; Bs[nb][lk + 1][row] = vb.y;
                Bs[nb][lk + 2][row] = vb.z; Bs[nb][lk + 3][row] = vb.w;
            }
        }
        #pragma unroll
        for (int kk = 0; kk < 16; kk++) {
            float a[8];
            *(float4*)&a[0] = *(const float4*)&As[buf][kk][ty * 8];
            *(float4*)&a[4] = *(const float4*)&As[buf][kk][ty * 8 + 4];
            union { float4 q[2]; unsigned long long ll[4]; } bu;
            bu.q[0] = *(const float4*)&Bs[buf][kk][tx * 8];
            bu.q[1] = *(const float4*)&Bs[buf][kk][tx * 8 + 4];
            unsigned long long a2[8];
            #pragma unroll
            for (int u = 0; u < 8; u++) a2[u] = splat2(a[u]);
            #pragma unroll
            for (int u = 0; u < 8; u++)
                #pragma unroll
                for (int v = 0; v < 4; v++)
                    ffma2(acc[u][v], a2[u], bu.ll[v], acc[u][v]);
        }
        __syncthreads();
        buf ^= 1;
    }

    int colbase = blockIdx.x * 128 + tx * 8;
    float bbr[8];
    *(float4*)&bbr[0] = *(const float4*)&g_bb[colbase];
    *(float4*)&bbr[4] = *(const float4*)&g_bb[colbase + 4];
    #pragma unroll
    for (int u = 0; u < 8; u++) {
        float r[8];
        #pragma unroll
        for (int v = 0; v < 4; v++) {
            unsigned int lo, hi;
            asm("mov.b64 {%0, %1}, %2;" : "=r"(lo), "=r"(hi) : "l"(acc[u][v]));
            r[2 * v]     = __uint_as_float(lo);
            r[2 * v + 1] = __uint_as_float(hi);
        }
        size_t ro = (size_t)(blockIdx.y * 128 + ty * 8 + u) * N + colbase;
        float4 o0, o1;
        o0.x = bbr[0] - 2.f * r[0];
        o0.y = bbr[1] - 2.f * r[1];
        o0.z = bbr[2] - 2.f * r[2];
        o0.w = bbr[3] - 2.f * r[3];
        o1.x = bbr[4] - 2.f * r[4];
        o1.y = bbr[5] - 2.f * r[5];
        o1.z = bbr[6] - 2.f * r[6];
        o1.w = bbr[7] - 2.f * r[7];
        *(float4*)&g_S[ro]     = o0;
        *(float4*)&g_S[ro + 4] = o1;
    }
}

// ---------------------------------------------------------------
// warp-cooperative top-K smallest (value, index), jax tie-break
// ---------------------------------------------------------------
template <int K>
__device__ __forceinline__ void topk_warp(const float* __restrict__ Srow, int N, int lane,
                                          float* out_v, int* out_i) {
    float v[K]; int ix[K];
    #pragma unroll
    for (int t = 0; t < K; t++) { v[t] = INFINITY; ix[t] = 0x7fffffff; }
    for (int j = lane; j < N; j += 32) {
        float s = Srow[j];
        bool better = (s < v[K - 1]) || (s == v[K - 1] && j < ix[K - 1]);
        if (better) {
            v[K - 1] = s; ix[K - 1] = j;
            #pragma unroll
            for (int t = K - 1; t > 0; t--) {
                bool sw = (v[t] < v[t - 1]) || (v[t] == v[t - 1] && ix[t] < ix[t - 1]);
                float tv = sw ? v[t - 1] : v[t];
                float bv = sw ? v[t] : v[t - 1];
                int   ti = sw ? ix[t - 1] : ix[t];
                int   bi = sw ? ix[t] : ix[t - 1];
                v[t] = tv; v[t - 1] = bv; ix[t] = ti; ix[t - 1] = bi;
            }
        }
    }
    #pragma unroll
    for (int r = 0; r < K; r++) {
        float bv = v[0]; int bi = ix[0];
        #pragma unroll
        for (int o = 16; o > 0; o >>= 1) {
            float ov = __shfl_xor_sync(0xffffffffu, bv, o);
            int   oi = __shfl_xor_sync(0xffffffffu, bi, o);
            if (ov < bv || (ov == bv && oi < bi)) { bv = ov; bi = oi; }
        }
        out_v[r] = bv; out_i[r] = bi;
        if (bv == v[0] && bi == ix[0]) {   // unique owner pops
            #pragma unroll
            for (int t = 0; t < K - 1; t++) { v[t] = v[t + 1]; ix[t] = ix[t + 1]; }
            v[K - 1] = INFINITY; ix[K - 1] = 0x7fffffff;
        }
    }
}

// torch.mode semantics: most frequent, smallest value on tie
template <int K>
__device__ __forceinline__ float mode_k(const float* lab) {
    float best = 0.f; int bc = -1;
    #pragma unroll
    for (int a = 0; a < K; a++) {
        int c = 0;
        #pragma unroll
        for (int b = 0; b < K; b++) c += (lab[a] == lab[b]);
        if (c > bc || (c == bc && lab[a] < best)) { bc = c; best = lab[a]; }
    }
    return best;
}

__global__ void topk_mixup_kernel() {
    int warp = (blockIdx.x * blockDim.x + threadIdx.x) >> 5;
    int lane = threadIdx.x & 31;
    if (warp >= N0) return;
    const float* Srow = g_S + (size_t)warp * N0;
    float rv[11]; int ri[11];
    topk_warp<11>(Srow, N0, lane, rv, ri);
    if (lane == 0) {
        float lab[11];
        #pragma unroll
        for (int t = 0; t < 11; t++) lab[t] = g_y2[ri[t]];
        g_y2[N0 + warp] = mode_k<11>(lab);
    }
}

__global__ void topk_knn_kernel() {
    int warp = (blockIdx.x * blockDim.x + threadIdx.x) >> 5;
    int lane = threadIdx.x & 31;
    if (warp >= NUM) return;
    const float* Srow = g_S + (size_t)warp * NUM;
    float rv[4]; int ri[4];
    topk_warp<4>(Srow, NUM, lane, rv, ri);
    if (lane == 0) {
        float lab[3];
        lab[0] = g_y2[ri[1]]; lab[1] = g_y2[ri[2]]; lab[2] = g_y2[ri[3]];
        float m = mode_k<3>(lab);
        float d = m - g_y2[warp];
        g_ptknn[warp] = d * d;
    }
}

// ---------------------------------------------------------------
// class statistics
// ---------------------------------------------------------------
__global__ void zero_stats_kernel() {
    int i = blockIdx.x * blockDim.x + threadIdx.x;
    if (i < CLASSES * DD) g_musum[i] = 0.f;
    if (i < CLASSES)      g_cnt[i]   = 0.f;
}

__global__ void scatter_kernel() {   // grid NUM, block 128
    int i = blockIdx.x;
    int tid = threadIdx.x;
    int c = (int)g_y2[i];
    const float* xr = g_x2 + (size_t)i * DD;
    for (int d = tid; d < DD; d += 128)
        atomicAdd(&g_musum[c * DD + d], xr[d]);
    if (tid == 0) atomicAdd(&g_cnt[c], 1.f);
}

__global__ void mu_kernel() {        // grid CLASSES, block 128
    int c = blockIdx.x, tid = threadIdx.x;
    float inv = 1.f / fmaxf(g_cnt[c], 1.f);
    float ss = 0.f;
    for (int d = tid; d < DD; d += 128) {
        float m = g_musum[c * DD + d] * inv;
        g_mu[c * DD + d] = m;
        ss += m * m;
    }
    __shared__ float red[128];
    red[tid] = ss;
    __syncthreads();
    #pragma unroll
    for (int s = 64; s > 0; s >>= 1) {
        if (tid < s) red[tid] += red[tid + s];
        __syncthreads();
    }
    if (tid == 0) g_mumu[c] = red[0];
}

// gm loss per point: grid NUM, block 128 (thread c < 100 owns class c)
__global__ void gm_kernel() {
    int i = blockIdx.x, tid = threadIdx.x;
    __shared__ float xs[DD];
    for (int d = tid; d < DD; d += 128) xs[d] = g_x2[(size_t)i * DD + d];
    __syncthreads();

    float w = 0.f;
    int c = tid;
    if (c < CLASSES) {
        const float4* mu4 = (const float4*)(g_mu + c * DD);
        const float4* xs4 = (const float4*)xs;
        float dot = 0.f;
        #pragma unroll 4
        for (int k = 0; k < DD / 4; k++) {
            float4 a = xs4[k], b = mu4[k];
            dot = fmaf(a.x, b.x, dot);
            dot = fmaf(a.y, b.y, dot);
            dot = fmaf(a.z, b.z, dot);
            dot = fmaf(a.w, b.w, dot);
        }
        float d2 = g_bb[i] + g_mumu[c] - 2.f * dot;
        w = (g_cnt[c] > 0.f) ? expf(-0.5f * d2) : 0.f;
    }
    __shared__ float red[128];
    red[tid] = w;
    __syncthreads();
    #pragma unroll
    for (int s = 64; s > 0; s >>= 1) {
        if (tid < s) red[tid] += red[tid + s];
        __syncthreads();
    }
    float wsum = red[0];
    __syncthreads();

    float t = 0.f;
    if (c < CLASSES) {
        float p = w / (wsum + 1e-15f);
        p = fminf(fmaxf(p, 0.f), 1.f);
        int yi = (int)g_y2[i];
        float dd = p - ((c == yi) ? 1.f : 0.f);
        t = dd * dd;
    }
    red[tid] = t;
    __syncthreads();
    #pragma unroll
    for (int s = 64; s > 0; s >>= 1) {
        if (tid < s) red[tid] += red[tid + s];
        __syncthreads();
    }
    if (tid == 0) g_ptgm[i] = red[0];
}

__global__ void final_kernel(float* __restrict__ out) {
    __shared__ float red[256];
    int tid = threadIdx.x;
    float s1 = 0.f, s2 = 0.f;
    for (int i = tid; i < NUM; i += 256) { s1 += g_ptgm[i]; s2 += g_ptknn[i]; }
    red[tid] = s1;
    __syncthreads();
    #pragma unroll
    for (int s = 128; s > 0; s >>= 1) {
        if (tid < s) red[tid] += red[tid + s];
        __syncthreads();
    }
    float t1 = red[0];
    __syncthreads();
    red[tid] = s2;
    __syncthreads();
    #pragma unroll
    for (int s = 128; s > 0; s >>= 1) {
        if (tid < s) red[tid] += red[tid + s];
        __syncthreads();
    }
    if (tid == 0) out[0] = t1 / (float)NUM + 0.01f * red[0] / (float)NUM;
}

// ---------------------------------------------------------------
extern "C" void kernel_launch(void* const* d_in, const int* in_sizes, int n_in,
                              void* d_out, int out_size) {
    const float* x    = (const float*)d_in[0];
    const float* y    = (const float*)d_in[1];
    const float* lam  = (const float*)d_in[2];
    const int*   perm = (const int*)d_in[3];
    float* out = (float*)d_out;

    build_kernel<<<NUM, 128>>>(x, y, lam, perm);

    // mixup distances: queries x_ul (rows N0..), base x (rows 0..N0)
    dim3 g1(N0 / 128, N0 / 128);
    gemm_dist<<<g1, 256>>>(N0, N0, N0);
    topk_mixup_kernel<<<N0 / 8, 256>>>();

    // knn distances over concatenated set
    dim3 g2(NUM / 128, NUM / 128);
    gemm_dist<<<g2, 256>>>(0, NUM, NUM);
    topk_knn_kernel<<<NUM / 8, 256>>>();

    // class stats + gm loss
    zero_stats_kernel<<<(CLASSES * DD + 255) / 256, 256>>>();
    scatter_kernel<<<NUM, 128>>>();
    mu_kernel<<<CLASSES, 128>>>();
    gm_kernel<<<NUM, 128>>>();

    final_kernel<<<1, 256>>>(out);
}

// round 4
// speedup vs baseline: 1.9093x; 1.9093x over previous
#include <cuda_runtime.h>
#include <cuda_bf16.h>
#include <cstdint>

#define N0      4096
#define NUM     8192
#define DD      512
#define KSP     1536          // split K: [h | h | l] vs [h | l | h]
#define CLASSES 100
#define NCH     24            // 1536 / 64
#define GEMM_SMEM 65536       // 2 bufs x (16KB A + 16KB B)

// ---- device scratch ----
__device__ float g_x2[(size_t)NUM * DD];
__device__ float g_bb[NUM];
__device__ float g_y2[NUM];
__device__ float g_S[(size_t)NUM * NUM];
__device__ __nv_bfloat16 g_A2[(size_t)NUM * KSP];   // split(-2*x2)
__device__ __nv_bfloat16 g_B2[(size_t)NUM * KSP];   // split(x2)
__device__ float g_musum[CLASSES * DD];
__device__ float g_cnt[CLASSES];
__device__ float g_mu[CLASSES * DD];
__device__ float g_mumu[CLASSES];
__device__ float g_ptgm[NUM];
__device__ float g_ptknn[NUM];

__device__ __forceinline__ uint32_t smem_u32(const void* p) {
    uint32_t a;
    asm("{ .reg .u64 t; cvta.to.shared.u64 t, %1; cvt.u32.u64 %0, t; }" : "=r"(a) : "l"(p));
    return a;
}
__device__ __forceinline__ void cp16(uint32_t dst, const void* src) {
    asm volatile("cp.async.cg.shared.global [%0], [%1], 16;" :: "r"(dst), "l"(src));
}
__device__ __forceinline__ void ldm_x4(uint32_t addr, uint32_t& d0, uint32_t& d1,
                                       uint32_t& d2, uint32_t& d3) {
    asm volatile("ldmatrix.sync.aligned.m8n8.x4.shared.b16 {%0,%1,%2,%3}, [%4];"
                 : "=r"(d0), "=r"(d1), "=r"(d2), "=r"(d3) : "r"(addr));
}
__device__ __forceinline__ void mma_bf16(float* c, const uint32_t* a, uint32_t b0, uint32_t b1) {
    asm volatile("mma.sync.aligned.m16n8k16.row.col.f32.bf16.bf16.f32 "
                 "{%0,%1,%2,%3},{%4,%5,%6,%7},{%8,%9},{%0,%1,%2,%3};"
                 : "+f"(c[0]), "+f"(c[1]), "+f"(c[2]), "+f"(c[3])
                 : "r"(a[0]), "r"(a[1]), "r"(a[2]), "r"(a[3]), "r"(b0), "r"(b1));
}

// ---------------------------------------------------------------
// build: x2, bb, y lower half, and bf16 split operands
// ---------------------------------------------------------------
__global__ void build_kernel(const float* __restrict__ x, const float* __restrict__ y,
                             const float* __restrict__ lamp, const int* __restrict__ perm) {
    int row = blockIdx.x;
    int tid = threadIdx.x;
    float4 v;
    if (row < N0) {
        v = ((const float4*)(x + (size_t)row * DD))[tid];
        if (tid == 0) g_y2[row] = y[row];
    } else {
        int j = row - N0;
        float lam = *lamp, oml = 1.f - lam;
        int p = perm[j];
        float4 va = ((const float4*)(x + (size_t)j * DD))[tid];
        float4 vb = ((const float4*)(x + (size_t)p * DD))[tid];
        v.x = va.x * lam + vb.x * oml;
        v.y = va.y * lam + vb.y * oml;
        v.z = va.z * lam + vb.z * oml;
        v.w = va.w * lam + vb.w * oml;
    }
    ((float4*)(g_x2 + (size_t)row * DD))[tid] = v;
    float ss = v.x * v.x + v.y * v.y + v.z * v.z + v.w * v.w;

    float f[4] = {v.x, v.y, v.z, v.w};
    __nv_bfloat16* A = g_A2 + (size_t)row * KSP;
    __nv_bfloat16* B = g_B2 + (size_t)row * KSP;
    #pragma unroll
    for (int e = 0; e < 4; e++) {
        int d = tid * 4 + e;
        float fb = f[e];
        __nv_bfloat16 hb = __float2bfloat16(fb);
        __nv_bfloat16 lb = __float2bfloat16(fb - __bfloat162float(hb));
        float fa = -2.f * fb;
        __nv_bfloat16 ha = __float2bfloat16(fa);
        __nv_bfloat16 la = __float2bfloat16(fa - __bfloat162float(ha));
        A[d] = ha; A[d + 512] = ha; A[d + 1024] = la;
        B[d] = hb; B[d + 512] = lb; B[d + 1024] = hb;
    }

    __shared__ float red[128];
    red[tid] = ss;
    __syncthreads();
    #pragma unroll
    for (int s = 64; s > 0; s >>= 1) {
        if (tid < s) red[tid] += red[tid + s];
        __syncthreads();
    }
    if (tid == 0) g_bb[row] = red[0];
}

// ---------------------------------------------------------------
// mma.sync distance GEMM: S[r][c] = bb[c] + sum_k A2[qoff+r][k]*B2[c][k]
// CTA 128x128, 8 warps (2x4 of 64x32), BK=64, K=1536, cp.async pipelined
// ---------------------------------------------------------------
__global__ __launch_bounds__(256, 2) void gemm_mma(int qoff, int Nn) {
    extern __shared__ char smem[];
    const int tid  = threadIdx.x;
    const int lane = tid & 31;
    const int w    = tid >> 5;
    const int wm   = w >> 2, wn = w & 3;
    const uint32_t sbase = smem_u32(smem);

    const char* gA = (const char*)(g_A2 + (size_t)(qoff + blockIdx.y * 128) * KSP);
    const char* gB = (const char*)(g_B2 + (size_t)(blockIdx.x * 128) * KSP);

    const int lrow = tid >> 3;   // 0..31
    const int lseg = tid & 7;

    float acc[4][4][4];
    #pragma unroll
    for (int mt = 0; mt < 4; mt++)
        #pragma unroll
        for (int nt = 0; nt < 4; nt++)
            #pragma unroll
            for (int e = 0; e < 4; e++) acc[mt][nt][e] = 0.f;

    // ---- async loader for chunk -> buffer ----
    #define ISSUE(chunk, buf)                                                        \
    {                                                                                \
        uint32_t sA = sbase + (buf) * 32768;                                         \
        uint32_t sB = sA + 16384;                                                    \
        _Pragma("unroll")                                                            \
        for (int r = 0; r < 4; r++) {                                                \
            int row = lrow + r * 32;                                                 \
            uint32_t d = (uint32_t)(row * 128 + ((lseg ^ (row & 7)) * 16));          \
            cp16(sA + d, gA + (size_t)row * (KSP * 2) + (chunk) * 128 + lseg * 16);  \
            cp16(sB + d, gB + (size_t)row * (KSP * 2) + (chunk) * 128 + lseg * 16);  \
        }                                                                            \
        asm volatile("cp.async.commit_group;" ::: "memory");                         \
    }

    ISSUE(0, 0);
    for (int i = 0; i < NCH; i++) {
        const int buf = i & 1;
        if (i + 1 < NCH) {
            ISSUE(i + 1, buf ^ 1);
            asm volatile("cp.async.wait_group 1;" ::: "memory");
        } else {
            asm volatile("cp.async.wait_group 0;" ::: "memory");
        }
        __syncthreads();

        const uint32_t sA = sbase + buf * 32768;
        const uint32_t sB = sA + 16384;
        #pragma unroll
        for (int kk = 0; kk < 4; kk++) {
            uint32_t a[4][4];
            const int ahalf = lane >> 4;                 // 0/1
            #pragma unroll
            for (int mt = 0; mt < 4; mt++) {
                int row = wm * 64 + mt * 16 + (lane & 15);
                uint32_t ad = sA + row * 128 + (((kk * 2 + ahalf) ^ (row & 7)) * 16);
                ldm_x4(ad, a[mt][0], a[mt][1], a[mt][2], a[mt][3]);
            }
            uint32_t b[2][4];
            #pragma unroll
            for (int pt = 0; pt < 2; pt++) {
                int nrow = wn * 32 + pt * 16 + ((lane >> 3) & 1) * 8 + (lane & 7);
                uint32_t bd = sB + nrow * 128 + (((kk * 2 + ahalf) ^ (nrow & 7)) * 16);
                ldm_x4(bd, b[pt][0], b[pt][1], b[pt][2], b[pt][3]);
            }
            #pragma unroll
            for (int mt = 0; mt < 4; mt++)
                #pragma unroll
                for (int nt = 0; nt < 4; nt++) {
                    int pt = nt >> 1, sub = nt & 1;
                    mma_bf16(acc[mt][nt], a[mt], b[pt][sub], b[pt][sub + 2]);
                }
        }
        __syncthreads();
    }
    #undef ISSUE

    // ---- epilogue: S = bb[col] + acc ----
    const int mbase = blockIdx.y * 128 + wm * 64;
    const int nbase = blockIdx.x * 128 + wn * 32;
    const int r0 = lane >> 2;
    const int c0 = (lane & 3) * 2;
    float bbv[4][2];
    #pragma unroll
    for (int nt = 0; nt < 4; nt++) {
        int col = nbase + nt * 8 + c0;
        bbv[nt][0] = g_bb[col];
        bbv[nt][1] = g_bb[col + 1];
    }
    #pragma unroll
    for (int mt = 0; mt < 4; mt++) {
        int m0 = mbase + mt * 16 + r0;
        #pragma unroll
        for (int nt = 0; nt < 4; nt++) {
            int col = nbase + nt * 8 + c0;
            float2 v0, v1;
            v0.x = bbv[nt][0] + acc[mt][nt][0];
            v0.y = bbv[nt][1] + acc[mt][nt][1];
            v1.x = bbv[nt][0] + acc[mt][nt][2];
            v1.y = bbv[nt][1] + acc[mt][nt][3];
            *(float2*)&g_S[(size_t)m0 * Nn + col]       = v0;
            *(float2*)&g_S[(size_t)(m0 + 8) * Nn + col] = v1;
        }
    }
}

// ---------------------------------------------------------------
// warp-cooperative top-K smallest (value, index), jax tie-break
// ---------------------------------------------------------------
template <int K>
__device__ __forceinline__ void topk_warp(const float* __restrict__ Srow, int N, int lane,
                                          float* out_v, int* out_i) {
    float v[K]; int ix[K];
    #pragma unroll
    for (int t = 0; t < K; t++) { v[t] = INFINITY; ix[t] = 0x7fffffff; }
    for (int j = lane; j < N; j += 32) {
        float s = Srow[j];
        bool better = (s < v[K - 1]) || (s == v[K - 1] && j < ix[K - 1]);
        if (better) {
            v[K - 1] = s; ix[K - 1] = j;
            #pragma unroll
            for (int t = K - 1; t > 0; t--) {
                bool sw = (v[t] < v[t - 1]) || (v[t] == v[t - 1] && ix[t] < ix[t - 1]);
                float tv = sw ? v[t - 1] : v[t];
                float bv = sw ? v[t] : v[t - 1];
                int   ti = sw ? ix[t - 1] : ix[t];
                int   bi = sw ? ix[t] : ix[t - 1];
                v[t] = tv; v[t - 1] = bv; ix[t] = ti; ix[t - 1] = bi;
            }
        }
    }
    #pragma unroll
    for (int r = 0; r < K; r++) {
        float bv = v[0]; int bi = ix[0];
        #pragma unroll
        for (int o = 16; o > 0; o >>= 1) {
            float ov = __shfl_xor_sync(0xffffffffu, bv, o);
            int   oi = __shfl_xor_sync(0xffffffffu, bi, o);
            if (ov < bv || (ov == bv && oi < bi)) { bv = ov; bi = oi; }
        }
        out_v[r] = bv; out_i[r] = bi;
        if (bv == v[0] && bi == ix[0]) {
            #pragma unroll
            for (int t = 0; t < K - 1; t++) { v[t] = v[t + 1]; ix[t] = ix[t + 1]; }
            v[K - 1] = INFINITY; ix[K - 1] = 0x7fffffff;
        }
    }
}

template <int K>
__device__ __forceinline__ float mode_k(const float* lab) {
    float best = 0.f; int bc = -1;
    #pragma unroll
    for (int a = 0; a < K; a++) {
        int c = 0;
        #pragma unroll
        for (int b = 0; b < K; b++) c += (lab[a] == lab[b]);
        if (c > bc || (c == bc && lab[a] < best)) { bc = c; best = lab[a]; }
    }
    return best;
}

__global__ void topk_mixup_kernel() {
    int warp = (blockIdx.x * blockDim.x + threadIdx.x) >> 5;
    int lane = threadIdx.x & 31;
    if (warp >= N0) return;
    const float* Srow = g_S + (size_t)warp * N0;
    float rv[11]; int ri[11];
    topk_warp<11>(Srow, N0, lane, rv, ri);
    if (lane == 0) {
        float lab[11];
        #pragma unroll
        for (int t = 0; t < 11; t++) lab[t] = g_y2[ri[t]];
        g_y2[N0 + warp] = mode_k<11>(lab);
    }
}

__global__ void topk_knn_kernel() {
    int warp = (blockIdx.x * blockDim.x + threadIdx.x) >> 5;
    int lane = threadIdx.x & 31;
    if (warp >= NUM) return;
    const float* Srow = g_S + (size_t)warp * NUM;
    float rv[4]; int ri[4];
    topk_warp<4>(Srow, NUM, lane, rv, ri);
    if (lane == 0) {
        float lab[3];
        lab[0] = g_y2[ri[1]]; lab[1] = g_y2[ri[2]]; lab[2] = g_y2[ri[3]];
        float m = mode_k<3>(lab);
        float d = m - g_y2[warp];
        g_ptknn[warp] = d * d;
    }
}

// ---------------------------------------------------------------
// class statistics + gm loss + final reduce
// ---------------------------------------------------------------
__global__ void zero_stats_kernel() {
    int i = blockIdx.x * blockDim.x + threadIdx.x;
    if (i < CLASSES * DD) g_musum[i] = 0.f;
    if (i < CLASSES)      g_cnt[i]   = 0.f;
}

__global__ void scatter_kernel() {
    int i = blockIdx.x;
    int tid = threadIdx.x;
    int c = (int)g_y2[i];
    const float* xr = g_x2 + (size_t)i * DD;
    for (int d = tid; d < DD; d += 128)
        atomicAdd(&g_musum[c * DD + d], xr[d]);
    if (tid == 0) atomicAdd(&g_cnt[c], 1.f);
}

__global__ void mu_kernel() {
    int c = blockIdx.x, tid = threadIdx.x;
    float inv = 1.f / fmaxf(g_cnt[c], 1.f);
    float ss = 0.f;
    for (int d = tid; d < DD; d += 128) {
        float m = g_musum[c * DD + d] * inv;
        g_mu[c * DD + d] = m;
        ss += m * m;
    }
    __shared__ float red[128];
    red[tid] = ss;
    __syncthreads();
    #pragma unroll
    for (int s = 64; s > 0; s >>= 1) {
        if (tid < s) red[tid] += red[tid + s];
        __syncthreads();
    }
    if (tid == 0) g_mumu[c] = red[0];
}

__global__ void gm_kernel() {
    int i = blockIdx.x, tid = threadIdx.x;
    __shared__ float xs[DD];
    for (int d = tid; d < DD; d += 128) xs[d] = g_x2[(size_t)i * DD + d];
    __syncthreads();

    float w = 0.f;
    int c = tid;
    if (c < CLASSES) {
        const float4* mu4 = (const float4*)(g_mu + c * DD);
        const float4* xs4 = (const float4*)xs;
        float dot = 0.f;
        #pragma unroll 4
        for (int k = 0; k < DD / 4; k++) {
            float4 a = xs4[k], b = mu4[k];
            dot = fmaf(a.x, b.x, dot);
            dot = fmaf(a.y, b.y, dot);
            dot = fmaf(a.z, b.z, dot);
            dot = fmaf(a.w, b.w, dot);
        }
        float d2 = g_bb[i] + g_mumu[c] - 2.f * dot;
        w = (g_cnt[c] > 0.f) ? expf(-0.5f * d2) : 0.f;
    }
    __shared__ float red[128];
    red[tid] = w;
    __syncthreads();
    #pragma unroll
    for (int s = 64; s > 0; s >>= 1) {
        if (tid < s) red[tid] += red[tid + s];
        __syncthreads();
    }
    float wsum = red[0];
    __syncthreads();

    float t = 0.f;
    if (c < CLASSES) {
        float p = w / (wsum + 1e-15f);
        p = fminf(fmaxf(p, 0.f), 1.f);
        int yi = (int)g_y2[i];
        float dd = p - ((c == yi) ? 1.f : 0.f);
        t = dd * dd;
    }
    red[tid] = t;
    __syncthreads();
    #pragma unroll
    for (int s = 64; s > 0; s >>= 1) {
        if (tid < s) red[tid] += red[tid + s];
        __syncthreads();
    }
    if (tid == 0) g_ptgm[i] = red[0];
}

__global__ void final_kernel(float* __restrict__ out) {
    __shared__ float red[256];
    int tid = threadIdx.x;
    float s1 = 0.f, s2 = 0.f;
    for (int i = tid; i < NUM; i += 256) { s1 += g_ptgm[i]; s2 += g_ptknn[i]; }
    red[tid] = s1;
    __syncthreads();
    #pragma unroll
    for (int s = 128; s > 0; s >>= 1) {
        if (tid < s) red[tid] += red[tid + s];
        __syncthreads();
    }
    float t1 = red[0];
    __syncthreads();
    red[tid] = s2;
    __syncthreads();
    #pragma unroll
    for (int s = 128; s > 0; s >>= 1) {
        if (tid < s) red[tid] += red[tid + s];
        __syncthreads();
    }
    if (tid == 0) out[0] = t1 / (float)NUM + 0.01f * red[0] / (float)NUM;
}

// ---------------------------------------------------------------
extern "C" void kernel_launch(void* const* d_in, const int* in_sizes, int n_in,
                              void* d_out, int out_size) {
    const float* x    = (const float*)d_in[0];
    const float* y    = (const float*)d_in[1];
    const float* lam  = (const float*)d_in[2];
    const int*   perm = (const int*)d_in[3];
    float* out = (float*)d_out;

    cudaFuncSetAttribute(gemm_mma, cudaFuncAttributeMaxDynamicSharedMemorySize, GEMM_SMEM);

    build_kernel<<<NUM, 128>>>(x, y, lam, perm);

    // mixup: queries x_ul (rows N0..), base x (cols 0..N0)
    dim3 g1(N0 / 128, N0 / 128);
    gemm_mma<<<g1, 256, GEMM_SMEM>>>(N0, N0);
    topk_mixup_kernel<<<N0 / 8, 256>>>();

    // knn over concatenated set
    dim3 g2(NUM / 128, NUM / 128);
    gemm_mma<<<g2, 256, GEMM_SMEM>>>(0, NUM);
    topk_knn_kernel<<<NUM / 8, 256>>>();

    zero_stats_kernel<<<(CLASSES * DD + 255) / 256, 256>>>();
    scatter_kernel<<<NUM, 128>>>();
    mu_kernel<<<CLASSES, 128>>>();
    gm_kernel<<<NUM, 128>>>();

    final_kernel<<<1, 256>>>(out);
}

// round 5
// speedup vs baseline: 2.3486x; 1.2301x over previous
#include <cuda_runtime.h>
#include <cuda_bf16.h>
#include <cstdint>

#define N0      4096
#define NUM     8192
#define DD      512
#define KSP     1536          // split K: [h | h | l] vs [h | l | h]
#define CLASSES 100
#define NCH     24            // 1536 / 64
#define STAGE_BYTES 49152     // 16KB A + 32KB B
#define GEMM_SMEM (3 * STAGE_BYTES)

// ---- device scratch ----
__device__ float g_x2[(size_t)NUM * DD];
__device__ float g_bb[NUM];
__device__ float g_y2[NUM];
__device__ float g_S[(size_t)NUM * NUM];
__device__ __nv_bfloat16 g_A2[(size_t)NUM * KSP];   // split(-2*x2)
__device__ __nv_bfloat16 g_B2[(size_t)NUM * KSP];   // split(x2)
__device__ float g_musum[CLASSES * DD];
__device__ float g_cnt[CLASSES];
__device__ float g_mu[CLASSES * DD];
__device__ float g_mumu[CLASSES];
__device__ float g_ptgm[NUM];
__device__ float g_ptknn[NUM];

__device__ __forceinline__ uint32_t smem_u32(const void* p) {
    uint32_t a;
    asm("{ .reg .u64 t; cvta.to.shared.u64 t, %1; cvt.u32.u64 %0, t; }" : "=r"(a) : "l"(p));
    return a;
}
__device__ __forceinline__ void cp16(uint32_t dst, const void* src) {
    asm volatile("cp.async.cg.shared.global [%0], [%1], 16;" :: "r"(dst), "l"(src));
}
__device__ __forceinline__ void ldm_x4(uint32_t addr, uint32_t& d0, uint32_t& d1,
                                       uint32_t& d2, uint32_t& d3) {
    asm volatile("ldmatrix.sync.aligned.m8n8.x4.shared.b16 {%0,%1,%2,%3}, [%4];"
                 : "=r"(d0), "=r"(d1), "=r"(d2), "=r"(d3) : "r"(addr));
}
__device__ __forceinline__ void mma_bf16(float* c, const uint32_t* a, uint32_t b0, uint32_t b1) {
    asm volatile("mma.sync.aligned.m16n8k16.row.col.f32.bf16.bf16.f32 "
                 "{%0,%1,%2,%3},{%4,%5,%6,%7},{%8,%9},{%0,%1,%2,%3};"
                 : "+f"(c[0]), "+f"(c[1]), "+f"(c[2]), "+f"(c[3])
                 : "r"(a[0]), "r"(a[1]), "r"(a[2]), "r"(a[3]), "r"(b0), "r"(b1));
}

// ---------------------------------------------------------------
// build: x2, bb, y lower half, and bf16 split operands
// ---------------------------------------------------------------
__global__ void build_kernel(const float* __restrict__ x, const float* __restrict__ y,
                             const float* __restrict__ lamp, const int* __restrict__ perm) {
    int row = blockIdx.x;
    int tid = threadIdx.x;
    float4 v;
    if (row < N0) {
        v = ((const float4*)(x + (size_t)row * DD))[tid];
        if (tid == 0) g_y2[row] = y[row];
    } else {
        int j = row - N0;
        float lam = *lamp, oml = 1.f - lam;
        int p = perm[j];
        float4 va = ((const float4*)(x + (size_t)j * DD))[tid];
        float4 vb = ((const float4*)(x + (size_t)p * DD))[tid];
        v.x = va.x * lam + vb.x * oml;
        v.y = va.y * lam + vb.y * oml;
        v.z = va.z * lam + vb.z * oml;
        v.w = va.w * lam + vb.w * oml;
    }
    ((float4*)(g_x2 + (size_t)row * DD))[tid] = v;
    float ss = v.x * v.x + v.y * v.y + v.z * v.z + v.w * v.w;

    float f[4] = {v.x, v.y, v.z, v.w};
    __nv_bfloat16* A = g_A2 + (size_t)row * KSP;
    __nv_bfloat16* B = g_B2 + (size_t)row * KSP;
    #pragma unroll
    for (int e = 0; e < 4; e++) {
        int d = tid * 4 + e;
        float fb = f[e];
        __nv_bfloat16 hb = __float2bfloat16(fb);
        __nv_bfloat16 lb = __float2bfloat16(fb - __bfloat162float(hb));
        float fa = -2.f * fb;
        __nv_bfloat16 ha = __float2bfloat16(fa);
        __nv_bfloat16 la = __float2bfloat16(fa - __bfloat162float(ha));
        A[d] = ha; A[d + 512] = ha; A[d + 1024] = la;
        B[d] = hb; B[d + 512] = lb; B[d + 1024] = hb;
    }

    __shared__ float red[128];
    red[tid] = ss;
    __syncthreads();
    #pragma unroll
    for (int s = 64; s > 0; s >>= 1) {
        if (tid < s) red[tid] += red[tid + s];
        __syncthreads();
    }
    if (tid == 0) g_bb[row] = red[0];
}

// ---------------------------------------------------------------
// mma.sync distance GEMM: S[r][c] = bb[c] + sum_k A2[qoff+r][k]*B2[c][k]
// CTA 128x256, 8 warps (2x4), warp tile 64x64, BK=64, 3-stage cp.async
// ---------------------------------------------------------------
__global__ __launch_bounds__(256) void gemm_mma(int qoff, int Nn) {
    extern __shared__ char smem[];
    const int tid  = threadIdx.x;
    const int lane = tid & 31;
    const int w    = tid >> 5;
    const int wm   = w >> 2, wn = w & 3;
    const uint32_t sbase = smem_u32(smem);

    const char* gA = (const char*)(g_A2 + (size_t)(qoff + blockIdx.y * 128) * KSP);
    const char* gB = (const char*)(g_B2 + (size_t)(blockIdx.x * 256) * KSP);

    const int lrow = tid >> 3;   // 0..31
    const int lseg = tid & 7;

    float acc[4][8][4];
    #pragma unroll
    for (int mt = 0; mt < 4; mt++)
        #pragma unroll
        for (int nt = 0; nt < 8; nt++)
            #pragma unroll
            for (int e = 0; e < 4; e++) acc[mt][nt][e] = 0.f;

    #define ISSUE(chunk, stg)                                                        \
    {                                                                                \
        uint32_t sA = sbase + (stg) * STAGE_BYTES;                                   \
        uint32_t sB = sA + 16384;                                                    \
        _Pragma("unroll")                                                            \
        for (int r = 0; r < 4; r++) {                                                \
            int row = lrow + r * 32;                                                 \
            uint32_t d = (uint32_t)(row * 128 + ((lseg ^ (row & 7)) * 16));          \
            cp16(sA + d, gA + (size_t)row * (KSP * 2) + (chunk) * 128 + lseg * 16);  \
        }                                                                            \
        _Pragma("unroll")                                                            \
        for (int r = 0; r < 8; r++) {                                                \
            int row = lrow + r * 32;                                                 \
            uint32_t d = (uint32_t)(row * 128 + ((lseg ^ (row & 7)) * 16));          \
            cp16(sB + d, gB + (size_t)row * (KSP * 2) + (chunk) * 128 + lseg * 16);  \
        }                                                                            \
        asm volatile("cp.async.commit_group;" ::: "memory");                         \
    }

    ISSUE(0, 0);
    ISSUE(1, 1);
    int stg = 0;
    for (int i = 0; i < NCH; i++) {
        if (i + 2 < NCH) {
            int ns = stg + 2; if (ns >= 3) ns -= 3;
            ISSUE(i + 2, ns);
            asm volatile("cp.async.wait_group 2;" ::: "memory");
        } else if (i + 1 < NCH) {
            asm volatile("cp.async.wait_group 1;" ::: "memory");
        } else {
            asm volatile("cp.async.wait_group 0;" ::: "memory");
        }
        __syncthreads();

        const uint32_t sA = sbase + stg * STAGE_BYTES;
        const uint32_t sB = sA + 16384;
        #pragma unroll
        for (int kk = 0; kk < 4; kk++) {
            const int half = lane >> 4;
            uint32_t a[4][4];
            #pragma unroll
            for (int mt = 0; mt < 4; mt++) {
                int row = wm * 64 + mt * 16 + (lane & 15);
                uint32_t ad = sA + row * 128 + (((kk * 2 + half) ^ (row & 7)) * 16);
                ldm_x4(ad, a[mt][0], a[mt][1], a[mt][2], a[mt][3]);
            }
            uint32_t b[4][4];
            #pragma unroll
            for (int nt = 0; nt < 4; nt++) {
                int nrow = wn * 64 + nt * 16 + ((lane >> 3) & 1) * 8 + (lane & 7);
                uint32_t bd = sB + nrow * 128 + (((kk * 2 + half) ^ (nrow & 7)) * 16);
                ldm_x4(bd, b[nt][0], b[nt][1], b[nt][2], b[nt][3]);
            }
            #pragma unroll
            for (int mt = 0; mt < 4; mt++)
                #pragma unroll
                for (int nt = 0; nt < 4; nt++) {
                    #pragma unroll
                    for (int sub = 0; sub < 2; sub++)
                        mma_bf16(acc[mt][nt * 2 + sub], a[mt], b[nt][sub], b[nt][sub + 2]);
                }
        }
        __syncthreads();
        stg++; if (stg == 3) stg = 0;
    }
    #undef ISSUE

    // ---- epilogue: S = bb[col] + acc ----
    const int mbase = blockIdx.y * 128 + wm * 64;
    const int nbase = blockIdx.x * 256 + wn * 64;
    const int r0 = lane >> 2;
    const int c0 = (lane & 3) * 2;
    float bbv[8][2];
    #pragma unroll
    for (int nt = 0; nt < 8; nt++) {
        int col = nbase + nt * 8 + c0;
        bbv[nt][0] = g_bb[col];
        bbv[nt][1] = g_bb[col + 1];
    }
    #pragma unroll
    for (int mt = 0; mt < 4; mt++) {
        int m0 = mbase + mt * 16 + r0;
        #pragma unroll
        for (int nt = 0; nt < 8; nt++) {
            int col = nbase + nt * 8 + c0;
            float2 v0, v1;
            v0.x = bbv[nt][0] + acc[mt][nt][0];
            v0.y = bbv[nt][1] + acc[mt][nt][1];
            v1.x = bbv[nt][0] + acc[mt][nt][2];
            v1.y = bbv[nt][1] + acc[mt][nt][3];
            *(float2*)&g_S[(size_t)m0 * Nn + col]       = v0;
            *(float2*)&g_S[(size_t)(m0 + 8) * Nn + col] = v1;
        }
    }
}

// ---------------------------------------------------------------
// warp-cooperative top-K smallest (value, index), jax tie-break
// float4-batched scan for MLP
// ---------------------------------------------------------------
template <int K>
__device__ __forceinline__ void topk_warp(const float* __restrict__ Srow, int N, int lane,
                                          float* out_v, int* out_i) {
    float v[K]; int ix[K];
    #pragma unroll
    for (int t = 0; t < K; t++) { v[t] = INFINITY; ix[t] = 0x7fffffff; }
    for (int base = 0; base < N; base += 128) {
        float4 q = *(const float4*)(Srow + base + lane * 4);
        float sv[4] = {q.x, q.y, q.z, q.w};
        #pragma unroll
        for (int e = 0; e < 4; e++) {
            float s = sv[e];
            int j = base + lane * 4 + e;
            bool better = (s < v[K - 1]) || (s == v[K - 1] && j < ix[K - 1]);
            if (better) {
                v[K - 1] = s; ix[K - 1] = j;
                #pragma unroll
                for (int t = K - 1; t > 0; t--) {
                    bool sw = (v[t] < v[t - 1]) || (v[t] == v[t - 1] && ix[t] < ix[t - 1]);
                    float tv = sw ? v[t - 1] : v[t];
                    float bv = sw ? v[t] : v[t - 1];
                    int   ti = sw ? ix[t - 1] : ix[t];
                    int   bi = sw ? ix[t] : ix[t - 1];
                    v[t] = tv; v[t - 1] = bv; ix[t] = ti; ix[t - 1] = bi;
                }
            }
        }
    }
    #pragma unroll
    for (int r = 0; r < K; r++) {
        float bv = v[0]; int bi = ix[0];
        #pragma unroll
        for (int o = 16; o > 0; o >>= 1) {
            float ov = __shfl_xor_sync(0xffffffffu, bv, o);
            int   oi = __shfl_xor_sync(0xffffffffu, bi, o);
            if (ov < bv || (ov == bv && oi < bi)) { bv = ov; bi = oi; }
        }
        out_v[r] = bv; out_i[r] = bi;
        if (bv == v[0] && bi == ix[0]) {
            #pragma unroll
            for (int t = 0; t < K - 1; t++) { v[t] = v[t + 1]; ix[t] = ix[t + 1]; }
            v[K - 1] = INFINITY; ix[K - 1] = 0x7fffffff;
        }
    }
}

template <int K>
__device__ __forceinline__ float mode_k(const float* lab) {
    float best = 0.f; int bc = -1;
    #pragma unroll
    for (int a = 0; a < K; a++) {
        int c = 0;
        #pragma unroll
        for (int b = 0; b < K; b++) c += (lab[a] == lab[b]);
        if (c > bc || (c == bc && lab[a] < best)) { bc = c; best = lab[a]; }
    }
    return best;
}

__global__ void topk_mixup_kernel() {
    int warp = (blockIdx.x * blockDim.x + threadIdx.x) >> 5;
    int lane = threadIdx.x & 31;
    if (warp >= N0) return;
    const float* Srow = g_S + (size_t)warp * N0;
    float rv[11]; int ri[11];
    topk_warp<11>(Srow, N0, lane, rv, ri);
    if (lane == 0) {
        float lab[11];
        #pragma unroll
        for (int t = 0; t < 11; t++) lab[t] = g_y2[ri[t]];
        g_y2[N0 + warp] = mode_k<11>(lab);
    }
}

__global__ void topk_knn_kernel() {
    int warp = (blockIdx.x * blockDim.x + threadIdx.x) >> 5;
    int lane = threadIdx.x & 31;
    if (warp >= NUM) return;
    const float* Srow = g_S + (size_t)warp * NUM;
    float rv[4]; int ri[4];
    topk_warp<4>(Srow, NUM, lane, rv, ri);
    if (lane == 0) {
        float lab[3];
        lab[0] = g_y2[ri[1]]; lab[1] = g_y2[ri[2]]; lab[2] = g_y2[ri[3]];
        float m = mode_k<3>(lab);
        float d = m - g_y2[warp];
        g_ptknn[warp] = d * d;
    }
}

// ---------------------------------------------------------------
// class statistics + gm loss + final reduce
// ---------------------------------------------------------------
__global__ void zero_stats_kernel() {
    int i = blockIdx.x * blockDim.x + threadIdx.x;
    if (i < CLASSES * DD) g_musum[i] = 0.f;
    if (i < CLASSES)      g_cnt[i]   = 0.f;
}

__global__ void scatter_kernel() {
    int i = blockIdx.x;
    int tid = threadIdx.x;
    int c = (int)g_y2[i];
    const float* xr = g_x2 + (size_t)i * DD;
    for (int d = tid; d < DD; d += 128)
        atomicAdd(&g_musum[c * DD + d], xr[d]);
    if (tid == 0) atomicAdd(&g_cnt[c], 1.f);
}

__global__ void mu_kernel() {
    int c = blockIdx.x, tid = threadIdx.x;
    float inv = 1.f / fmaxf(g_cnt[c], 1.f);
    float ss = 0.f;
    for (int d = tid; d < DD; d += 128) {
        float m = g_musum[c * DD + d] * inv;
        g_mu[c * DD + d] = m;
        ss += m * m;
    }
    __shared__ float red[128];
    red[tid] = ss;
    __syncthreads();
    #pragma unroll
    for (int s = 64; s > 0; s >>= 1) {
        if (tid < s) red[tid] += red[tid + s];
        __syncthreads();
    }
    if (tid == 0) g_mumu[c] = red[0];
}

// 8 points per block; mu value loaded once feeds 8 independent chains
#define GMP 8
__global__ void gm_kernel() {
    int i0 = blockIdx.x * GMP, tid = threadIdx.x;
    __shared__ float xs[GMP][DD];
    for (int t = tid; t < GMP * DD / 4; t += 128) {
        int p = t / (DD / 4), k = t % (DD / 4);
        ((float4*)xs[p])[k] = ((const float4*)(g_x2 + (size_t)(i0 + p) * DD))[k];
    }
    __syncthreads();

    int c = tid;
    float w[GMP];
    #pragma unroll
    for (int p = 0; p < GMP; p++) w[p] = 0.f;
    if (c < CLASSES) {
        const float4* mu4 = (const float4*)(g_mu + c * DD);
        float dot[GMP];
        #pragma unroll
        for (int p = 0; p < GMP; p++) dot[p] = 0.f;
        for (int k = 0; k < DD / 4; k++) {
            float4 b = mu4[k];
            #pragma unroll
            for (int p = 0; p < GMP; p++) {
                float4 a = ((const float4*)xs[p])[k];
                dot[p] = fmaf(a.x, b.x, dot[p]);
                dot[p] = fmaf(a.y, b.y, dot[p]);
                dot[p] = fmaf(a.z, b.z, dot[p]);
                dot[p] = fmaf(a.w, b.w, dot[p]);
            }
        }
        float live = (g_cnt[c] > 0.f) ? 1.f : 0.f;
        #pragma unroll
        for (int p = 0; p < GMP; p++) {
            float d2 = g_bb[i0 + p] + g_mumu[c] - 2.f * dot[p];
            w[p] = live * expf(-0.5f * d2);
        }
    }
    __shared__ float red[128];
    for (int p = 0; p < GMP; p++) {
        red[tid] = w[p];
        __syncthreads();
        #pragma unroll
        for (int s = 64; s > 0; s >>= 1) {
            if (tid < s) red[tid] += red[tid + s];
            __syncthreads();
        }
        float wsum = red[0];
        __syncthreads();
        float t = 0.f;
        if (c < CLASSES) {
            float pp = w[p] / (wsum + 1e-15f);
            pp = fminf(fmaxf(pp, 0.f), 1.f);
            int yi = (int)g_y2[i0 + p];
            float dd = pp - ((c == yi) ? 1.f : 0.f);
            t = dd * dd;
        }
        red[tid] = t;
        __syncthreads();
        #pragma unroll
        for (int s = 64; s > 0; s >>= 1) {
            if (tid < s) red[tid] += red[tid + s];
            __syncthreads();
        }
        if (tid == 0) g_ptgm[i0 + p] = red[0];
        __syncthreads();
    }
}

__global__ void final_kernel(float* __restrict__ out) {
    __shared__ float red[256];
    int tid = threadIdx.x;
    float s1 = 0.f, s2 = 0.f;
    for (int i = tid; i < NUM; i += 256) { s1 += g_ptgm[i]; s2 += g_ptknn[i]; }
    red[tid] = s1;
    __syncthreads();
    #pragma unroll
    for (int s = 128; s > 0; s >>= 1) {
        if (tid < s) red[tid] += red[tid + s];
        __syncthreads();
    }
    float t1 = red[0];
    __syncthreads();
    red[tid] = s2;
    __syncthreads();
    #pragma unroll
    for (int s = 128; s > 0; s >>= 1) {
        if (tid < s) red[tid] += red[tid + s];
        __syncthreads();
    }
    if (tid == 0) out[0] = t1 / (float)NUM + 0.01f * red[0] / (float)NUM;
}

// ---------------------------------------------------------------
extern "C" void kernel_launch(void* const* d_in, const int* in_sizes, int n_in,
                              void* d_out, int out_size) {
    const float* x    = (const float*)d_in[0];
    const float* y    = (const float*)d_in[1];
    const float* lam  = (const float*)d_in[2];
    const int*   perm = (const int*)d_in[3];
    float* out = (float*)d_out;

    cudaFuncSetAttribute(gemm_mma, cudaFuncAttributeMaxDynamicSharedMemorySize, GEMM_SMEM);

    build_kernel<<<NUM, 128>>>(x, y, lam, perm);

    // mixup: queries x_ul (rows N0..), base x (cols 0..N0)
    dim3 g1(N0 / 256, N0 / 128);
    gemm_mma<<<g1, 256, GEMM_SMEM>>>(N0, N0);
    topk_mixup_kernel<<<N0 / 8, 256>>>();

    // knn over concatenated set
    dim3 g2(NUM / 256, NUM / 128);
    gemm_mma<<<g2, 256, GEMM_SMEM>>>(0, NUM);
    topk_knn_kernel<<<NUM / 8, 256>>>();

    zero_stats_kernel<<<(CLASSES * DD + 255) / 256, 256>>>();
    scatter_kernel<<<NUM, 128>>>();
    mu_kernel<<<CLASSES, 128>>>();
    gm_kernel<<<NUM / GMP, 128>>>();

    final_kernel<<<1, 256>>>(out);
}

// round 6
// speedup vs baseline: 2.9596x; 1.2601x over previous
#include <cuda_runtime.h>
#include <cuda_bf16.h>
#include <cstdint>

#define N0      4096
#define NUM     8192
#define DD      512
#define KSP     1536          // split K: [h | h | l] vs [h | l | h]
#define CLASSES 100
#define NCH     24            // 1536 / 64
#define STAGE_BYTES 32768     // 16KB A + 16KB B
#define GEMM_SMEM (2 * STAGE_BYTES)

// ---- device scratch ----
__device__ float g_x2[(size_t)NUM * DD];
__device__ float g_bb[NUM];
__device__ float g_y2[NUM];
__device__ float g_S[(size_t)NUM * NUM];
__device__ __nv_bfloat16 g_A2[(size_t)NUM * KSP];   // split(-2*x2)
__device__ __nv_bfloat16 g_B2[(size_t)NUM * KSP];   // split(x2)
__device__ float g_musum[CLASSES * DD];
__device__ float g_cnt[CLASSES];
__device__ float g_mu[CLASSES * DD];
__device__ float g_mumu[CLASSES];
__device__ float g_ptgm[NUM];
__device__ float g_ptknn[NUM];

__device__ __forceinline__ uint32_t smem_u32(const void* p) {
    uint32_t a;
    asm("{ .reg .u64 t; cvta.to.shared.u64 t, %1; cvt.u32.u64 %0, t; }" : "=r"(a) : "l"(p));
    return a;
}
__device__ __forceinline__ void cp16(uint32_t dst, const void* src) {
    asm volatile("cp.async.cg.shared.global [%0], [%1], 16;" :: "r"(dst), "l"(src));
}
__device__ __forceinline__ void ldm_x4(uint32_t addr, uint32_t& d0, uint32_t& d1,
                                       uint32_t& d2, uint32_t& d3) {
    asm volatile("ldmatrix.sync.aligned.m8n8.x4.shared.b16 {%0,%1,%2,%3}, [%4];"
                 : "=r"(d0), "=r"(d1), "=r"(d2), "=r"(d3) : "r"(addr));
}
__device__ __forceinline__ void mma_bf16(float* c, const uint32_t* a, uint32_t b0, uint32_t b1) {
    asm volatile("mma.sync.aligned.m16n8k16.row.col.f32.bf16.bf16.f32 "
                 "{%0,%1,%2,%3},{%4,%5,%6,%7},{%8,%9},{%0,%1,%2,%3};"
                 : "+f"(c[0]), "+f"(c[1]), "+f"(c[2]), "+f"(c[3])
                 : "r"(a[0]), "r"(a[1]), "r"(a[2]), "r"(a[3]), "r"(b0), "r"(b1));
}

// ---------------------------------------------------------------
// build: x2, bb, y lower half, and bf16 split operands
// ---------------------------------------------------------------
__global__ void build_kernel(const float* __restrict__ x, const float* __restrict__ y,
                             const float* __restrict__ lamp, const int* __restrict__ perm) {
    int row = blockIdx.x;
    int tid = threadIdx.x;
    float4 v;
    if (row < N0) {
        v = ((const float4*)(x + (size_t)row * DD))[tid];
        if (tid == 0) g_y2[row] = y[row];
    } else {
        int j = row - N0;
        float lam = *lamp, oml = 1.f - lam;
        int p = perm[j];
        float4 va = ((const float4*)(x + (size_t)j * DD))[tid];
        float4 vb = ((const float4*)(x + (size_t)p * DD))[tid];
        v.x = va.x * lam + vb.x * oml;
        v.y = va.y * lam + vb.y * oml;
        v.z = va.z * lam + vb.z * oml;
        v.w = va.w * lam + vb.w * oml;
    }
    ((float4*)(g_x2 + (size_t)row * DD))[tid] = v;
    float ss = v.x * v.x + v.y * v.y + v.z * v.z + v.w * v.w;

    float f[4] = {v.x, v.y, v.z, v.w};
    __nv_bfloat16* A = g_A2 + (size_t)row * KSP;
    __nv_bfloat16* B = g_B2 + (size_t)row * KSP;
    #pragma unroll
    for (int e = 0; e < 4; e++) {
        int d = tid * 4 + e;
        float fb = f[e];
        __nv_bfloat16 hb = __float2bfloat16(fb);
        __nv_bfloat16 lb = __float2bfloat16(fb - __bfloat162float(hb));
        float fa = -2.f * fb;
        __nv_bfloat16 ha = __float2bfloat16(fa);
        __nv_bfloat16 la = __float2bfloat16(fa - __bfloat162float(ha));
        A[d] = ha; A[d + 512] = ha; A[d + 1024] = la;
        B[d] = hb; B[d + 512] = lb; B[d + 1024] = hb;
    }

    __shared__ float red[128];
    red[tid] = ss;
    __syncthreads();
    #pragma unroll
    for (int s = 64; s > 0; s >>= 1) {
        if (tid < s) red[tid] += red[tid + s];
        __syncthreads();
    }
    if (tid == 0) g_bb[row] = red[0];
}

// ---------------------------------------------------------------
// mma.sync distance GEMM over the FULL 8192x8192 matrix:
// S[r][c] = bb[c] + sum_k A2[r][k]*B2[c][k]
// CTA 128x128, 4 warps (2x2), warp tile 64x64, BK=64, 2-stage cp.async
// ---------------------------------------------------------------
__global__ __launch_bounds__(128, 2) void gemm_mma() {
    extern __shared__ char smem[];
    const int tid  = threadIdx.x;
    const int lane = tid & 31;
    const int w    = tid >> 5;
    const int wm   = w >> 1, wn = w & 1;
    const uint32_t sbase = smem_u32(smem);

    const char* gA = (const char*)(g_A2 + (size_t)(blockIdx.y * 128) * KSP);
    const char* gB = (const char*)(g_B2 + (size_t)(blockIdx.x * 128) * KSP);

    const int lrow = tid >> 3;   // 0..15
    const int lseg = tid & 7;

    float acc[4][8][4];
    #pragma unroll
    for (int mt = 0; mt < 4; mt++)
        #pragma unroll
        for (int nt = 0; nt < 8; nt++)
            #pragma unroll
            for (int e = 0; e < 4; e++) acc[mt][nt][e] = 0.f;

    #define ISSUE(chunk, stg)                                                        \
    {                                                                                \
        uint32_t sA = sbase + (stg) * STAGE_BYTES;                                   \
        uint32_t sB = sA + 16384;                                                    \
        _Pragma("unroll")                                                            \
        for (int r = 0; r < 8; r++) {                                                \
            int row = lrow + r * 16;                                                 \
            uint32_t d = (uint32_t)(row * 128 + ((lseg ^ (row & 7)) * 16));          \
            cp16(sA + d, gA + (size_t)row * (KSP * 2) + (chunk) * 128 + lseg * 16);  \
            cp16(sB + d, gB + (size_t)row * (KSP * 2) + (chunk) * 128 + lseg * 16);  \
        }                                                                            \
        asm volatile("cp.async.commit_group;" ::: "memory");                         \
    }

    ISSUE(0, 0);
    for (int i = 0; i < NCH; i++) {
        const int stg = i & 1;
        if (i + 1 < NCH) {
            ISSUE(i + 1, stg ^ 1);
            asm volatile("cp.async.wait_group 1;" ::: "memory");
        } else {
            asm volatile("cp.async.wait_group 0;" ::: "memory");
        }
        __syncthreads();

        const uint32_t sA = sbase + stg * STAGE_BYTES;
        const uint32_t sB = sA + 16384;
        #pragma unroll
        for (int kk = 0; kk < 4; kk++) {
            const int half = lane >> 4;
            uint32_t a[4][4];
            #pragma unroll
            for (int mt = 0; mt < 4; mt++) {
                int row = wm * 64 + mt * 16 + (lane & 15);
                uint32_t ad = sA + row * 128 + (((kk * 2 + half) ^ (row & 7)) * 16);
                ldm_x4(ad, a[mt][0], a[mt][1], a[mt][2], a[mt][3]);
            }
            uint32_t b[4][4];
            #pragma unroll
            for (int nt = 0; nt < 4; nt++) {
                int nrow = wn * 64 + nt * 16 + ((lane >> 3) & 1) * 8 + (lane & 7);
                uint32_t bd = sB + nrow * 128 + (((kk * 2 + half) ^ (nrow & 7)) * 16);
                ldm_x4(bd, b[nt][0], b[nt][1], b[nt][2], b[nt][3]);
            }
            #pragma unroll
            for (int mt = 0; mt < 4; mt++)
                #pragma unroll
                for (int nt = 0; nt < 4; nt++) {
                    #pragma unroll
                    for (int sub = 0; sub < 2; sub++)
                        mma_bf16(acc[mt][nt * 2 + sub], a[mt], b[nt][sub], b[nt][sub + 2]);
                }
        }
        __syncthreads();
    }
    #undef ISSUE

    // ---- epilogue: S = bb[col] + acc ----
    const int mbase = blockIdx.y * 128 + wm * 64;
    const int nbase = blockIdx.x * 128 + wn * 64;
    const int r0 = lane >> 2;
    const int c0 = (lane & 3) * 2;
    float bbv[8][2];
    #pragma unroll
    for (int nt = 0; nt < 8; nt++) {
        int col = nbase + nt * 8 + c0;
        bbv[nt][0] = g_bb[col];
        bbv[nt][1] = g_bb[col + 1];
    }
    #pragma unroll
    for (int mt = 0; mt < 4; mt++) {
        int m0 = mbase + mt * 16 + r0;
        #pragma unroll
        for (int nt = 0; nt < 8; nt++) {
            int col = nbase + nt * 8 + c0;
            float2 v0, v1;
            v0.x = bbv[nt][0] + acc[mt][nt][0];
            v0.y = bbv[nt][1] + acc[mt][nt][1];
            v1.x = bbv[nt][0] + acc[mt][nt][2];
            v1.y = bbv[nt][1] + acc[mt][nt][3];
            *(float2*)&g_S[(size_t)m0 * NUM + col]       = v0;
            *(float2*)&g_S[(size_t)(m0 + 8) * NUM + col] = v1;
        }
    }
}

// ---------------------------------------------------------------
// warp-cooperative top-K smallest (value, index), jax tie-break
// float4-batched scan for MLP
// ---------------------------------------------------------------
template <int K>
__device__ __forceinline__ void topk_warp(const float* __restrict__ Srow, int N, int lane,
                                          float* out_v, int* out_i) {
    float v[K]; int ix[K];
    #pragma unroll
    for (int t = 0; t < K; t++) { v[t] = INFINITY; ix[t] = 0x7fffffff; }
    for (int base = 0; base < N; base += 128) {
        float4 q = *(const float4*)(Srow + base + lane * 4);
        float sv[4] = {q.x, q.y, q.z, q.w};
        #pragma unroll
        for (int e = 0; e < 4; e++) {
            float s = sv[e];
            int j = base + lane * 4 + e;
            bool better = (s < v[K - 1]) || (s == v[K - 1] && j < ix[K - 1]);
            if (better) {
                v[K - 1] = s; ix[K - 1] = j;
                #pragma unroll
                for (int t = K - 1; t > 0; t--) {
                    bool sw = (v[t] < v[t - 1]) || (v[t] == v[t - 1] && ix[t] < ix[t - 1]);
                    float tv = sw ? v[t - 1] : v[t];
                    float bv = sw ? v[t] : v[t - 1];
                    int   ti = sw ? ix[t - 1] : ix[t];
                    int   bi = sw ? ix[t] : ix[t - 1];
                    v[t] = tv; v[t - 1] = bv; ix[t] = ti; ix[t - 1] = bi;
                }
            }
        }
    }
    #pragma unroll
    for (int r = 0; r < K; r++) {
        float bv = v[0]; int bi = ix[0];
        #pragma unroll
        for (int o = 16; o > 0; o >>= 1) {
            float ov = __shfl_xor_sync(0xffffffffu, bv, o);
            int   oi = __shfl_xor_sync(0xffffffffu, bi, o);
            if (ov < bv || (ov == bv && oi < bi)) { bv = ov; bi = oi; }
        }
        out_v[r] = bv; out_i[r] = bi;
        if (bv == v[0] && bi == ix[0]) {
            #pragma unroll
            for (int t = 0; t < K - 1; t++) { v[t] = v[t + 1]; ix[t] = ix[t + 1]; }
            v[K - 1] = INFINITY; ix[K - 1] = 0x7fffffff;
        }
    }
}

template <int K>
__device__ __forceinline__ float mode_k(const float* lab) {
    float best = 0.f; int bc = -1;
    #pragma unroll
    for (int a = 0; a < K; a++) {
        int c = 0;
        #pragma unroll
        for (int b = 0; b < K; b++) c += (lab[a] == lab[b]);
        if (c > bc || (c == bc && lab[a] < best)) { bc = c; best = lab[a]; }
    }
    return best;
}

// mixup: 11-NN of x_ul among x = bottom-left quadrant of the full S matrix
__global__ void topk_mixup_kernel() {
    int warp = (blockIdx.x * blockDim.x + threadIdx.x) >> 5;
    int lane = threadIdx.x & 31;
    if (warp >= N0) return;
    const float* Srow = g_S + (size_t)(N0 + warp) * NUM;   // row 4096+warp, cols 0..4095
    float rv[11]; int ri[11];
    topk_warp<11>(Srow, N0, lane, rv, ri);
    if (lane == 0) {
        float lab[11];
        #pragma unroll
        for (int t = 0; t < 11; t++) lab[t] = g_y2[ri[t]];
        g_y2[N0 + warp] = mode_k<11>(lab);
    }
}

__global__ void topk_knn_kernel() {
    int warp = (blockIdx.x * blockDim.x + threadIdx.x) >> 5;
    int lane = threadIdx.x & 31;
    if (warp >= NUM) return;
    const float* Srow = g_S + (size_t)warp * NUM;
    float rv[4]; int ri[4];
    topk_warp<4>(Srow, NUM, lane, rv, ri);
    if (lane == 0) {
        float lab[3];
        lab[0] = g_y2[ri[1]]; lab[1] = g_y2[ri[2]]; lab[2] = g_y2[ri[3]];
        float m = mode_k<3>(lab);
        float d = m - g_y2[warp];
        g_ptknn[warp] = d * d;
    }
}

// ---------------------------------------------------------------
// class statistics + gm loss + final reduce
// ---------------------------------------------------------------
__global__ void zero_stats_kernel() {
    int i = blockIdx.x * blockDim.x + threadIdx.x;
    if (i < CLASSES * DD) g_musum[i] = 0.f;
    if (i < CLASSES)      g_cnt[i]   = 0.f;
}

__global__ void scatter_kernel() {
    int i = blockIdx.x;
    int tid = threadIdx.x;
    int c = (int)g_y2[i];
    const float* xr = g_x2 + (size_t)i * DD;
    for (int d = tid; d < DD; d += 128)
        atomicAdd(&g_musum[c * DD + d], xr[d]);
    if (tid == 0) atomicAdd(&g_cnt[c], 1.f);
}

__global__ void mu_kernel() {
    int c = blockIdx.x, tid = threadIdx.x;
    float inv = 1.f / fmaxf(g_cnt[c], 1.f);
    float ss = 0.f;
    for (int d = tid; d < DD; d += 128) {
        float m = g_musum[c * DD + d] * inv;
        g_mu[c * DD + d] = m;
        ss += m * m;
    }
    __shared__ float red[128];
    red[tid] = ss;
    __syncthreads();
    #pragma unroll
    for (int s = 64; s > 0; s >>= 1) {
        if (tid < s) red[tid] += red[tid + s];
        __syncthreads();
    }
    if (tid == 0) g_mumu[c] = red[0];
}

// 8 points per block; mu value loaded once feeds 8 independent chains
#define GMP 8
__global__ void gm_kernel() {
    int i0 = blockIdx.x * GMP, tid = threadIdx.x;
    __shared__ float xs[GMP][DD];
    for (int t = tid; t < GMP * DD / 4; t += 128) {
        int p = t / (DD / 4), k = t % (DD / 4);
        ((float4*)xs[p])[k] = ((const float4*)(g_x2 + (size_t)(i0 + p) * DD))[k];
    }
    __syncthreads();

    int c = tid;
    float w[GMP];
    #pragma unroll
    for (int p = 0; p < GMP; p++) w[p] = 0.f;
    if (c < CLASSES) {
        const float4* mu4 = (const float4*)(g_mu + c * DD);
        float dot[GMP];
        #pragma unroll
        for (int p = 0; p < GMP; p++) dot[p] = 0.f;
        for (int k = 0; k < DD / 4; k++) {
            float4 b = mu4[k];
            #pragma unroll
            for (int p = 0; p < GMP; p++) {
                float4 a = ((const float4*)xs[p])[k];
                dot[p] = fmaf(a.x, b.x, dot[p]);
                dot[p] = fmaf(a.y, b.y, dot[p]);
                dot[p] = fmaf(a.z, b.z, dot[p]);
                dot[p] = fmaf(a.w, b.w, dot[p]);
            }
        }
        float live = (g_cnt[c] > 0.f) ? 1.f : 0.f;
        #pragma unroll
        for (int p = 0; p < GMP; p++) {
            float d2 = g_bb[i0 + p] + g_mumu[c] - 2.f * dot[p];
            w[p] = live * expf(-0.5f * d2);
        }
    }
    __shared__ float red[128];
    for (int p = 0; p < GMP; p++) {
        red[tid] = w[p];
        __syncthreads();
        #pragma unroll
        for (int s = 64; s > 0; s >>= 1) {
            if (tid < s) red[tid] += red[tid + s];
            __syncthreads();
        }
        float wsum = red[0];
        __syncthreads();
        float t = 0.f;
        if (c < CLASSES) {
            float pp = w[p] / (wsum + 1e-15f);
            pp = fminf(fmaxf(pp, 0.f), 1.f);
            int yi = (int)g_y2[i0 + p];
            float dd = pp - ((c == yi) ? 1.f : 0.f);
            t = dd * dd;
        }
        red[tid] = t;
        __syncthreads();
        #pragma unroll
        for (int s = 64; s > 0; s >>= 1) {
            if (tid < s) red[tid] += red[tid + s];
            __syncthreads();
        }
        if (tid == 0) g_ptgm[i0 + p] = red[0];
        __syncthreads();
    }
}

__global__ void final_kernel(float* __restrict__ out) {
    __shared__ float red[256];
    int tid = threadIdx.x;
    float s1 = 0.f, s2 = 0.f;
    for (int i = tid; i < NUM; i += 256) { s1 += g_ptgm[i]; s2 += g_ptknn[i]; }
    red[tid] = s1;
    __syncthreads();
    #pragma unroll
    for (int s = 128; s > 0; s >>= 1) {
        if (tid < s) red[tid] += red[tid + s];
        __syncthreads();
    }
    float t1 = red[0];
    __syncthreads();
    red[tid] = s2;
    __syncthreads();
    #pragma unroll
    for (int s = 128; s > 0; s >>= 1) {
        if (tid < s) red[tid] += red[tid + s];
        __syncthreads();
    }
    if (tid == 0) out[0] = t1 / (float)NUM + 0.01f * red[0] / (float)NUM;
}

// ---------------------------------------------------------------
extern "C" void kernel_launch(void* const* d_in, const int* in_sizes, int n_in,
                              void* d_out, int out_size) {
    const float* x    = (const float*)d_in[0];
    const float* y    = (const float*)d_in[1];
    const float* lam  = (const float*)d_in[2];
    const int*   perm = (const int*)d_in[3];
    float* out = (float*)d_out;

    cudaFuncSetAttribute(gemm_mma, cudaFuncAttributeMaxDynamicSharedMemorySize, GEMM_SMEM);

    build_kernel<<<NUM, 128>>>(x, y, lam, perm);

    // ONE full 8192x8192 distance GEMM; mixup block is its bottom-left quadrant
    dim3 g2(NUM / 128, NUM / 128);
    gemm_mma<<<g2, 128, GEMM_SMEM>>>();

    topk_mixup_kernel<<<N0 / 8, 256>>>();
    topk_knn_kernel<<<NUM / 8, 256>>>();

    zero_stats_kernel<<<(CLASSES * DD + 255) / 256, 256>>>();
    scatter_kernel<<<NUM, 128>>>();
    mu_kernel<<<CLASSES, 128>>>();
    gm_kernel<<<NUM / GMP, 128>>>();

    final_kernel<<<1, 256>>>(out);
}

// round 8
// speedup vs baseline: 3.9161x; 1.3232x over previous
#include <cuda_runtime.h>
#include <cuda_bf16.h>
#include <cstdint>

#define N0      4096
#define NUM     8192
#define DD      512
#define KSP     1536          // split K: [h | h | l] vs [h | l | h]
#define CLASSES 100
#define NCH     24            // 1536 / 64
#define STAGE_BYTES 32768     // 16KB A + 16KB B
#define GEMM_SMEM (2 * STAGE_BYTES)

// ---- device scratch ----
__device__ float g_x2[(size_t)NUM * DD];
__device__ float g_bb[NUM];
__device__ float g_y2[NUM];
__device__ float g_S[(size_t)NUM * NUM];
__device__ __nv_bfloat16 g_A2[(size_t)NUM * KSP];   // split(-2*x2)
__device__ __nv_bfloat16 g_B2[(size_t)NUM * KSP];   // split(x2)
__device__ float g_musum[CLASSES * DD];
__device__ float g_cnt[CLASSES];
__device__ float g_mu[CLASSES * DD];
__device__ float g_mumu[CLASSES];
__device__ float g_ptgm[NUM];
__device__ float g_ptknn[NUM];

__device__ __forceinline__ uint32_t smem_u32(const void* p) {
    uint32_t a;
    asm("{ .reg .u64 t; cvta.to.shared.u64 t, %1; cvt.u32.u64 %0, t; }" : "=r"(a) : "l"(p));
    return a;
}
__device__ __forceinline__ void cp16(uint32_t dst, const void* src) {
    asm volatile("cp.async.cg.shared.global [%0], [%1], 16;" :: "r"(dst), "l"(src));
}
__device__ __forceinline__ void ldm_x4(uint32_t addr, uint32_t& d0, uint32_t& d1,
                                       uint32_t& d2, uint32_t& d3) {
    asm volatile("ldmatrix.sync.aligned.m8n8.x4.shared.b16 {%0,%1,%2,%3}, [%4];"
                 : "=r"(d0), "=r"(d1), "=r"(d2), "=r"(d3) : "r"(addr));
}
__device__ __forceinline__ void mma_bf16(float* c, const uint32_t* a, uint32_t b0, uint32_t b1) {
    asm volatile("mma.sync.aligned.m16n8k16.row.col.f32.bf16.bf16.f32 "
                 "{%0,%1,%2,%3},{%4,%5,%6,%7},{%8,%9},{%0,%1,%2,%3};"
                 : "+f"(c[0]), "+f"(c[1]), "+f"(c[2]), "+f"(c[3])
                 : "r"(a[0]), "r"(a[1]), "r"(a[2]), "r"(a[3]), "r"(b0), "r"(b1));
}

// ---------------------------------------------------------------
// build: x2, bb, y lower half, and bf16 split operands
// ---------------------------------------------------------------
__global__ void build_kernel(const float* __restrict__ x, const float* __restrict__ y,
                             const float* __restrict__ lamp, const int* __restrict__ perm) {
    int row = blockIdx.x;
    int tid = threadIdx.x;
    float4 v;
    if (row < N0) {
        v = ((const float4*)(x + (size_t)row * DD))[tid];
        if (tid == 0) g_y2[row] = y[row];
    } else {
        int j = row - N0;
        float lam = *lamp, oml = 1.f - lam;
        int p = perm[j];
        float4 va = ((const float4*)(x + (size_t)j * DD))[tid];
        float4 vb = ((const float4*)(x + (size_t)p * DD))[tid];
        v.x = va.x * lam + vb.x * oml;
        v.y = va.y * lam + vb.y * oml;
        v.z = va.z * lam + vb.z * oml;
        v.w = va.w * lam + vb.w * oml;
    }
    ((float4*)(g_x2 + (size_t)row * DD))[tid] = v;
    float ss = v.x * v.x + v.y * v.y + v.z * v.z + v.w * v.w;

    float f[4] = {v.x, v.y, v.z, v.w};
    __nv_bfloat16* A = g_A2 + (size_t)row * KSP;
    __nv_bfloat16* B = g_B2 + (size_t)row * KSP;
    #pragma unroll
    for (int e = 0; e < 4; e++) {
        int d = tid * 4 + e;
        float fb = f[e];
        __nv_bfloat16 hb = __float2bfloat16(fb);
        __nv_bfloat16 lb = __float2bfloat16(fb - __bfloat162float(hb));
        float fa = -2.f * fb;
        __nv_bfloat16 ha = __float2bfloat16(fa);
        __nv_bfloat16 la = __float2bfloat16(fa - __bfloat162float(ha));
        A[d] = ha; A[d + 512] = ha; A[d + 1024] = la;
        B[d] = hb; B[d + 512] = lb; B[d + 1024] = hb;
    }

    __shared__ float red[128];
    red[tid] = ss;
    __syncthreads();
    #pragma unroll
    for (int s = 64; s > 0; s >>= 1) {
        if (tid < s) red[tid] += red[tid + s];
        __syncthreads();
    }
    if (tid == 0) g_bb[row] = red[0];
}

// ---------------------------------------------------------------
// mma.sync distance GEMM, LOWER TRIANGLE of CTA tiles + mirror:
// S[r][c] = bb[c] + dot(r,c);  S[c][r] = bb[r] + dot(r,c)
// CTA 128x128, 4 warps (2x2), warp tile 64x64, BK=64, 2-stage cp.async
// ---------------------------------------------------------------
__global__ __launch_bounds__(128, 2) void gemm_mma() {
    const int bx = blockIdx.x, by = blockIdx.y;
    if (bx > by) return;                 // triangular: only bx <= by
    extern __shared__ char smem[];
    const int tid  = threadIdx.x;
    const int lane = tid & 31;
    const int w    = tid >> 5;
    const int wm   = w >> 1, wn = w & 1;
    const uint32_t sbase = smem_u32(smem);

    const char* gA = (const char*)(g_A2 + (size_t)(by * 128) * KSP);
    const char* gB = (const char*)(g_B2 + (size_t)(bx * 128) * KSP);

    const int lrow = tid >> 3;   // 0..15
    const int lseg = tid & 7;

    float acc[4][8][4];
    #pragma unroll
    for (int mt = 0; mt < 4; mt++)
        #pragma unroll
        for (int nt = 0; nt < 8; nt++)
            #pragma unroll
            for (int e = 0; e < 4; e++) acc[mt][nt][e] = 0.f;

    #define ISSUE(chunk, stg)                                                        \
    {                                                                                \
        uint32_t sA = sbase + (stg) * STAGE_BYTES;                                   \
        uint32_t sB = sA + 16384;                                                    \
        _Pragma("unroll")                                                            \
        for (int r = 0; r < 8; r++) {                                                \
            int row = lrow + r * 16;                                                 \
            uint32_t d = (uint32_t)(row * 128 + ((lseg ^ (row & 7)) * 16));          \
            cp16(sA + d, gA + (size_t)row * (KSP * 2) + (chunk) * 128 + lseg * 16);  \
            cp16(sB + d, gB + (size_t)row * (KSP * 2) + (chunk) * 128 + lseg * 16);  \
        }                                                                            \
        asm volatile("cp.async.commit_group;" ::: "memory");                         \
    }

    ISSUE(0, 0);
    for (int i = 0; i < NCH; i++) {
        const int stg = i & 1;
        if (i + 1 < NCH) {
            ISSUE(i + 1, stg ^ 1);
            asm volatile("cp.async.wait_group 1;" ::: "memory");
        } else {
            asm volatile("cp.async.wait_group 0;" ::: "memory");
        }
        __syncthreads();

        const uint32_t sA = sbase + stg * STAGE_BYTES;
        const uint32_t sB = sA + 16384;
        #pragma unroll
        for (int kk = 0; kk < 4; kk++) {
            const int half = lane >> 4;
            uint32_t a[4][4];
            #pragma unroll
            for (int mt = 0; mt < 4; mt++) {
                int row = wm * 64 + mt * 16 + (lane & 15);
                uint32_t ad = sA + row * 128 + (((kk * 2 + half) ^ (row & 7)) * 16);
                ldm_x4(ad, a[mt][0], a[mt][1], a[mt][2], a[mt][3]);
            }
            uint32_t b[4][4];
            #pragma unroll
            for (int nt = 0; nt < 4; nt++) {
                int nrow = wn * 64 + nt * 16 + ((lane >> 3) & 1) * 8 + (lane & 7);
                uint32_t bd = sB + nrow * 128 + (((kk * 2 + half) ^ (nrow & 7)) * 16);
                ldm_x4(bd, b[nt][0], b[nt][1], b[nt][2], b[nt][3]);
            }
            #pragma unroll
            for (int mt = 0; mt < 4; mt++)
                #pragma unroll
                for (int nt = 0; nt < 4; nt++) {
                    #pragma unroll
                    for (int sub = 0; sub < 2; sub++)
                        mma_bf16(acc[mt][nt * 2 + sub], a[mt], b[nt][sub], b[nt][sub + 2]);
                }
        }
        __syncthreads();
    }
    #undef ISSUE

    const int mb0 = by * 128, nb0 = bx * 128;
    const int r0 = lane >> 2;
    const int c0 = (lane & 3) * 2;

    // ---- straight tile: S[mb0+..][nb0+..] = bb[col] + acc ----
    {
        float bbv[8][2];
        #pragma unroll
        for (int nt = 0; nt < 8; nt++) {
            int col = nb0 + wn * 64 + nt * 8 + c0;
            bbv[nt][0] = g_bb[col];
            bbv[nt][1] = g_bb[col + 1];
        }
        #pragma unroll
        for (int mt = 0; mt < 4; mt++) {
            int m0 = mb0 + wm * 64 + mt * 16 + r0;
            #pragma unroll
            for (int nt = 0; nt < 8; nt++) {
                int col = nb0 + wn * 64 + nt * 8 + c0;
                float2 v0, v1;
                v0.x = bbv[nt][0] + acc[mt][nt][0];
                v0.y = bbv[nt][1] + acc[mt][nt][1];
                v1.x = bbv[nt][0] + acc[mt][nt][2];
                v1.y = bbv[nt][1] + acc[mt][nt][3];
                *(float2*)&g_S[(size_t)m0 * NUM + col]       = v0;
                *(float2*)&g_S[(size_t)(m0 + 8) * NUM + col] = v1;
            }
        }
    }

    // ---- mirrored tile (off-diagonal only): S[nb0+c][mb0+r] = bb[row]+acc ----
    if (bx != by) {
        float bbr[4][2];
        #pragma unroll
        for (int mt = 0; mt < 4; mt++) {
            int m0 = mb0 + wm * 64 + mt * 16 + r0;
            bbr[mt][0] = g_bb[m0];
            bbr[mt][1] = g_bb[m0 + 8];
        }
        float* stage = (float*)smem;     // [64][132] floats (stride mult of 4 -> aligned LD.128)
        #pragma unroll 1
        for (int h = 0; h < 2; h++) {
            __syncthreads();
            if (wn == h) {
                #pragma unroll
                for (int mt = 0; mt < 4; mt++) {
                    int rl = wm * 64 + mt * 16 + r0;
                    #pragma unroll
                    for (int nt = 0; nt < 8; nt++) {
                        int cl = nt * 8 + c0;
                        stage[cl * 132 + rl]           = bbr[mt][0] + acc[mt][nt][0];
                        stage[(cl + 1) * 132 + rl]     = bbr[mt][0] + acc[mt][nt][1];
                        stage[cl * 132 + rl + 8]       = bbr[mt][1] + acc[mt][nt][2];
                        stage[(cl + 1) * 132 + rl + 8] = bbr[mt][1] + acc[mt][nt][3];
                    }
                }
            }
            __syncthreads();
            int cl  = tid >> 1;            // 0..63
            int seg = (tid & 1) * 64;      // 0 or 64
            size_t orow = (size_t)(nb0 + h * 64 + cl) * NUM + mb0 + seg;
            #pragma unroll
            for (int k2 = 0; k2 < 16; k2++) {
                float4 vv = *(float4*)&stage[cl * 132 + seg + k2 * 4];
                *(float4*)&g_S[orow + k2 * 4] = vv;
            }
        }
    }
}

// ---------------------------------------------------------------
// warp-cooperative top-K smallest (value, index), jax tie-break
// float4 scan with vectorized-min fast path
// ---------------------------------------------------------------
template <int K>
__device__ __forceinline__ void topk_warp(const float* __restrict__ Srow, int N, int lane,
                                          float* out_v, int* out_i) {
    float v[K]; int ix[K];
    #pragma unroll
    for (int t = 0; t < K; t++) { v[t] = INFINITY; ix[t] = 0x7fffffff; }
    for (int base = 0; base < N; base += 128) {
        float4 q = *(const float4*)(Srow + base + lane * 4);
        float m = fminf(fminf(q.x, q.y), fminf(q.z, q.w));
        if (m <= v[K - 1]) {               // rare slow path (<= keeps index tie-break)
            float sv[4] = {q.x, q.y, q.z, q.w};
            #pragma unroll
            for (int e = 0; e < 4; e++) {
                float s = sv[e];
                int j = base + lane * 4 + e;
                bool better = (s < v[K - 1]) || (s == v[K - 1] && j < ix[K - 1]);
                if (better) {
                    v[K - 1] = s; ix[K - 1] = j;
                    #pragma unroll
                    for (int t = K - 1; t > 0; t--) {
                        bool sw = (v[t] < v[t - 1]) || (v[t] == v[t - 1] && ix[t] < ix[t - 1]);
                        float tv = sw ? v[t - 1] : v[t];
                        float bv = sw ? v[t] : v[t - 1];
                        int   ti = sw ? ix[t - 1] : ix[t];
                        int   bi = sw ? ix[t] : ix[t - 1];
                        v[t] = tv; v[t - 1] = bv; ix[t] = ti; ix[t - 1] = bi;
                    }
                }
            }
        }
    }
    #pragma unroll
    for (int r = 0; r < K; r++) {
        float bv = v[0]; int bi = ix[0];
        #pragma unroll
        for (int o = 16; o > 0; o >>= 1) {
            float ov = __shfl_xor_sync(0xffffffffu, bv, o);
            int   oi = __shfl_xor_sync(0xffffffffu, bi, o);
            if (ov < bv || (ov == bv && oi < bi)) { bv = ov; bi = oi; }
        }
        out_v[r] = bv; out_i[r] = bi;
        if (bv == v[0] && bi == ix[0]) {
            #pragma unroll
            for (int t = 0; t < K - 1; t++) { v[t] = v[t + 1]; ix[t] = ix[t + 1]; }
            v[K - 1] = INFINITY; ix[K - 1] = 0x7fffffff;
        }
    }
}

template <int K>
__device__ __forceinline__ float mode_k(const float* lab) {
    float best = 0.f; int bc = -1;
    #pragma unroll
    for (int a = 0; a < K; a++) {
        int c = 0;
        #pragma unroll
        for (int b = 0; b < K; b++) c += (lab[a] == lab[b]);
        if (c > bc || (c == bc && lab[a] < best)) { bc = c; best = lab[a]; }
    }
    return best;
}

// mixup: 11-NN of x_ul among x = bottom-left quadrant of the full S matrix
__global__ void topk_mixup_kernel() {
    int warp = (blockIdx.x * blockDim.x + threadIdx.x) >> 5;
    int lane = threadIdx.x & 31;
    if (warp >= N0) return;
    const float* Srow = g_S + (size_t)(N0 + warp) * NUM;   // row 4096+warp, cols 0..4095
    float rv[11]; int ri[11];
    topk_warp<11>(Srow, N0, lane, rv, ri);
    if (lane == 0) {
        float lab[11];
        #pragma unroll
        for (int t = 0; t < 11; t++) lab[t] = g_y2[ri[t]];
        g_y2[N0 + warp] = mode_k<11>(lab);
    }
}

__global__ void topk_knn_kernel() {
    int warp = (blockIdx.x * blockDim.x + threadIdx.x) >> 5;
    int lane = threadIdx.x & 31;
    if (warp >= NUM) return;
    const float* Srow = g_S + (size_t)warp * NUM;
    float rv[4]; int ri[4];
    topk_warp<4>(Srow, NUM, lane, rv, ri);
    if (lane == 0) {
        float lab[3];
        lab[0] = g_y2[ri[1]]; lab[1] = g_y2[ri[2]]; lab[2] = g_y2[ri[3]];
        float m = mode_k<3>(lab);
        float d = m - g_y2[warp];
        g_ptknn[warp] = d * d;
    }
}

// ---------------------------------------------------------------
// class statistics + gm loss + final reduce
// ---------------------------------------------------------------
__global__ void zero_stats_kernel() {
    int i = blockIdx.x * blockDim.x + threadIdx.x;
    if (i < CLASSES * DD) g_musum[i] = 0.f;
    if (i < CLASSES)      g_cnt[i]   = 0.f;
}

__global__ void scatter_kernel() {
    int i = blockIdx.x;
    int tid = threadIdx.x;
    int c = (int)g_y2[i];
    const float* xr = g_x2 + (size_t)i * DD;
    for (int d = tid; d < DD; d += 128)
        atomicAdd(&g_musum[c * DD + d], xr[d]);
    if (tid == 0) atomicAdd(&g_cnt[c], 1.f);
}

__global__ void mu_kernel() {
    int c = blockIdx.x, tid = threadIdx.x;
    float inv = 1.f / fmaxf(g_cnt[c], 1.f);
    float ss = 0.f;
    for (int d = tid; d < DD; d += 128) {
        float m = g_musum[c * DD + d] * inv;
        g_mu[c * DD + d] = m;
        ss += m * m;
    }
    __shared__ float red[128];
    red[tid] = ss;
    __syncthreads();
    #pragma unroll
    for (int s = 64; s > 0; s >>= 1) {
        if (tid < s) red[tid] += red[tid + s];
        __syncthreads();
    }
    if (tid == 0) g_mumu[c] = red[0];
}

// 8 points per block; mu value loaded once feeds 8 independent chains
#define GMP 8
__global__ void gm_kernel() {
    int i0 = blockIdx.x * GMP, tid = threadIdx.x;
    __shared__ float xs[GMP][DD];
    for (int t = tid; t < GMP * DD / 4; t += 128) {
        int p = t / (DD / 4), k = t % (DD / 4);
        ((float4*)xs[p])[k] = ((const float4*)(g_x2 + (size_t)(i0 + p) * DD))[k];
    }
    __syncthreads();

    int c = tid;
    float w[GMP];
    #pragma unroll
    for (int p = 0; p < GMP; p++) w[p] = 0.f;
    if (c < CLASSES) {
        const float4* mu4 = (const float4*)(g_mu + c * DD);
        float dot[GMP];
        #pragma unroll
        for (int p = 0; p < GMP; p++) dot[p] = 0.f;
        for (int k = 0; k < DD / 4; k++) {
            float4 b = mu4[k];
            #pragma unroll
            for (int p = 0; p < GMP; p++) {
                float4 a = ((const float4*)xs[p])[k];
                dot[p] = fmaf(a.x, b.x, dot[p]);
                dot[p] = fmaf(a.y, b.y, dot[p]);
                dot[p] = fmaf(a.z, b.z, dot[p]);
                dot[p] = fmaf(a.w, b.w, dot[p]);
            }
        }
        float live = (g_cnt[c] > 0.f) ? 1.f : 0.f;
        #pragma unroll
        for (int p = 0; p < GMP; p++) {
            float d2 = g_bb[i0 + p] + g_mumu[c] - 2.f * dot[p];
            w[p] = live * expf(-0.5f * d2);
        }
    }
    __shared__ float red[128];
    for (int p = 0; p < GMP; p++) {
        red[tid] = w[p];
        __syncthreads();
        #pragma unroll
        for (int s = 64; s > 0; s >>= 1) {
            if (tid < s) red[tid] += red[tid + s];
            __syncthreads();
        }
        float wsum = red[0];
        __syncthreads();
        float t = 0.f;
        if (c < CLASSES) {
            float pp = w[p] / (wsum + 1e-15f);
            pp = fminf(fmaxf(pp, 0.f), 1.f);
            int yi = (int)g_y2[i0 + p];
            float dd = pp - ((c == yi) ? 1.f : 0.f);
            t = dd * dd;
        }
        red[tid] = t;
        __syncthreads();
        #pragma unroll
        for (int s = 64; s > 0; s >>= 1) {
            if (tid < s) red[tid] += red[tid + s];
            __syncthreads();
        }
        if (tid == 0) g_ptgm[i0 + p] = red[0];
        __syncthreads();
    }
}

__global__ void final_kernel(float* __restrict__ out) {
    __shared__ float red[256];
    int tid = threadIdx.x;
    float s1 = 0.f, s2 = 0.f;
    for (int i = tid; i < NUM; i += 256) { s1 += g_ptgm[i]; s2 += g_ptknn[i]; }
    red[tid] = s1;
    __syncthreads();
    #pragma unroll
    for (int s = 128; s > 0; s >>= 1) {
        if (tid < s) red[tid] += red[tid + s];
        __syncthreads();
    }
    float t1 = red[0];
    __syncthreads();
    red[tid] = s2;
    __syncthreads();
    #pragma unroll
    for (int s = 128; s > 0; s >>= 1) {
        if (tid < s) red[tid] += red[tid + s];
        __syncthreads();
    }
    if (tid == 0) out[0] = t1 / (float)NUM + 0.01f * red[0] / (float)NUM;
}

// ---------------------------------------------------------------
extern "C" void kernel_launch(void* const* d_in, const int* in_sizes, int n_in,
                              void* d_out, int out_size) {
    const float* x    = (const float*)d_in[0];
    const float* y    = (const float*)d_in[1];
    const float* lam  = (const float*)d_in[2];
    const int*   perm = (const int*)d_in[3];
    float* out = (float*)d_out;

    cudaFuncSetAttribute(gemm_mma, cudaFuncAttributeMaxDynamicSharedMemorySize, GEMM_SMEM);

    build_kernel<<<NUM, 128>>>(x, y, lam, perm);

    // triangular distance GEMM (lower CTA tiles) + mirrored writes = full S
    dim3 g2(NUM / 128, NUM / 128);
    gemm_mma<<<g2, 128, GEMM_SMEM>>>();

    topk_mixup_kernel<<<N0 / 8, 256>>>();
    topk_knn_kernel<<<NUM / 8, 256>>>();

    zero_stats_kernel<<<(CLASSES * DD + 255) / 256, 256>>>();
    scatter_kernel<<<NUM, 128>>>();
    mu_kernel<<<CLASSES, 128>>>();
    gm_kernel<<<NUM / GMP, 128>>>();

    final_kernel<<<1, 256>>>(out);
}